// round 1
// baseline (speedup 1.0000x reference)
#include <cuda_runtime.h>

// ReadingLayerReLU: key = relu(x @ W^T); val[b] = key[b] @ mem[b]^T
// Shapes: x (8,2048,256) -> (16384,256); W (256,256); mem (8,1024,256)
// Out: key (16384*256) then val (16384*1024), fp32.

#define BM 128
#define BN 128
#define BK 8
#define TM 8
#define TN 8

template<bool RELU>
__global__ __launch_bounds__(256, 2)
void sgemm_nt_kernel(const float* __restrict__ A,
                     const float* __restrict__ B,
                     float* __restrict__ C,
                     int M, int N, int K,
                     long strideA, long strideB, long strideC)
{
    A += (long)blockIdx.z * strideA;
    B += (long)blockIdx.z * strideB;
    C += (long)blockIdx.z * strideC;

    __shared__ float As[BK][BM];
    __shared__ float Bs[BK][BN];

    const int tid = threadIdx.x;        // 0..255
    const int tx  = tid & 15;           // 0..15  (N direction)
    const int ty  = tid >> 4;           // 0..15  (M direction)

    // Global-load mapping: 256 threads, each loads one float4 per tile
    // A tile: BM x BK = 128x8 floats = 256 float4
    const int arow  = tid >> 1;         // 0..127
    const int acol4 = (tid & 1) * 4;    // 0 or 4
    const int brow  = tid >> 1;
    const int bcol4 = (tid & 1) * 4;

    const float* Ap = A + ((long)(blockIdx.y * BM + arow)) * K + acol4;
    const float* Bp = B + ((long)(blockIdx.x * BN + brow)) * K + bcol4;

    float acc[TM][TN];
    #pragma unroll
    for (int i = 0; i < TM; i++)
        #pragma unroll
        for (int j = 0; j < TN; j++)
            acc[i][j] = 0.0f;

    for (int k0 = 0; k0 < K; k0 += BK) {
        float4 av = *reinterpret_cast<const float4*>(Ap + k0);
        float4 bv = *reinterpret_cast<const float4*>(Bp + k0);

        As[acol4 + 0][arow] = av.x;
        As[acol4 + 1][arow] = av.y;
        As[acol4 + 2][arow] = av.z;
        As[acol4 + 3][arow] = av.w;

        Bs[bcol4 + 0][brow] = bv.x;
        Bs[bcol4 + 1][brow] = bv.y;
        Bs[bcol4 + 2][brow] = bv.z;
        Bs[bcol4 + 3][brow] = bv.w;

        __syncthreads();

        #pragma unroll
        for (int kk = 0; kk < BK; kk++) {
            float af[TM], bf[TN];
            #pragma unroll
            for (int i = 0; i < TM; i += 4) {
                float4 v = *reinterpret_cast<const float4*>(&As[kk][ty * TM + i]);
                af[i + 0] = v.x; af[i + 1] = v.y; af[i + 2] = v.z; af[i + 3] = v.w;
            }
            #pragma unroll
            for (int j = 0; j < TN; j += 4) {
                float4 v = *reinterpret_cast<const float4*>(&Bs[kk][tx * TN + j]);
                bf[j + 0] = v.x; bf[j + 1] = v.y; bf[j + 2] = v.z; bf[j + 3] = v.w;
            }
            #pragma unroll
            for (int i = 0; i < TM; i++)
                #pragma unroll
                for (int j = 0; j < TN; j++)
                    acc[i][j] = fmaf(af[i], bf[j], acc[i][j]);
        }

        __syncthreads();
    }

    // Store 8x8 block, vectorized float4
    const long crow0 = (long)blockIdx.y * BM + ty * TM;
    const long ccol0 = (long)blockIdx.x * BN + tx * TN;
    #pragma unroll
    for (int i = 0; i < TM; i++) {
        float* crow = C + (crow0 + i) * N + ccol0;
        #pragma unroll
        for (int j = 0; j < TN; j += 4) {
            float4 v;
            v.x = acc[i][j + 0];
            v.y = acc[i][j + 1];
            v.z = acc[i][j + 2];
            v.w = acc[i][j + 3];
            if (RELU) {
                v.x = fmaxf(v.x, 0.0f);
                v.y = fmaxf(v.y, 0.0f);
                v.z = fmaxf(v.z, 0.0f);
                v.w = fmaxf(v.w, 0.0f);
            }
            *reinterpret_cast<float4*>(crow + j) = v;
        }
    }
}

extern "C" void kernel_launch(void* const* d_in, const int* in_sizes, int n_in,
                              void* d_out, int out_size)
{
    (void)in_sizes; (void)n_in; (void)out_size;

    const float* x   = (const float*)d_in[0];  // (8,2048,256) -> (16384,256)
    const float* mem = (const float*)d_in[1];  // (8,1024,256)
    const float* W   = (const float*)d_in[2];  // (256,256)

    float* key = (float*)d_out;                       // 16384*256
    float* val = (float*)d_out + (long)16384 * 256;   // 16384*1024

    const int Bb = 8, S = 2048, I = 256, H = 256, Mm = 1024;
    const int Mrows = Bb * S;  // 16384

    // GEMM 1: key = relu(x @ W^T)   M=16384, N=256, K=256
    {
        dim3 grid(H / BN, Mrows / BM, 1);
        sgemm_nt_kernel<true><<<grid, 256>>>(x, W, key, Mrows, H, I, 0, 0, 0);
    }

    // GEMM 2: val[b] = key[b] @ mem[b]^T   M=2048, N=1024, K=256, batch=8
    {
        dim3 grid(Mm / BN, S / BM, Bb);
        sgemm_nt_kernel<false><<<grid, 256>>>(key, mem, val, S, Mm, H,
                                              (long)S * H, (long)Mm * H, (long)S * Mm);
    }
}

// round 4
// speedup vs baseline: 4.3141x; 4.3141x over previous
#include <cuda_runtime.h>
#include <cstdint>

// ReadingLayerReLU via mma.sync.m16n8k8 tf32 (legacy tensor path; tcgen05 PTX
// is rejected because the harness compiles for virtual arch compute_103).
// key = relu(x @ W^T)        : M=16384, N=256,  K=256
// val[b] = key[b] @ mem[b]^T : M=2048,  N=1024, K=256, batch=8
// Both NT (K contiguous in both operands).

#define BM 128
#define BN 128
#define BK 16
#define LDSS 20   // smem row stride in floats: row*20 mod 32 hits 8 distinct bank groups

__device__ __forceinline__ uint32_t f2tf32(float f) {
    uint32_t r;
    asm("cvt.rna.tf32.f32 %0, %1;" : "=r"(r) : "f"(f));
    return r;
}

template<bool RELU>
__global__ __launch_bounds__(256, 2)
void tf32_mma_nt(const float* __restrict__ A, const float* __restrict__ B,
                 float* __restrict__ C, int K, int N,
                 long sA, long sB, long sC)
{
    __shared__ uint32_t As[2][BM * LDSS];
    __shared__ uint32_t Bs[2][BN * LDSS];

    const int tid  = threadIdx.x;
    const int lane = tid & 31;
    const int warp = tid >> 5;
    const int wm   = warp >> 1;    // 0..3 -> M offset wm*32
    const int wn   = warp & 1;     // 0..1 -> N offset wn*64

    A += (long)blockIdx.z * sA + (long)blockIdx.y * BM * K;
    B += (long)blockIdx.z * sB + (long)blockIdx.x * BN * K;
    C += (long)blockIdx.z * sC;

    // Global-load mapping: per matrix 128x16 floats = 512 float4.
    // Thread handles rows r0 and r0+64, 4 floats at col c0.
    const int r0 = tid >> 2;          // 0..63
    const int c0 = (tid & 3) * 4;     // 0,4,8,12

    float4 la0, la1, lb0, lb1;

    const int nchunks = K / BK;       // 16

    // prologue: chunk 0
    {
        const float* Ap = A;
        const float* Bp = B;
        la0 = *(const float4*)(Ap + (long)r0        * K + c0);
        la1 = *(const float4*)(Ap + (long)(r0 + 64) * K + c0);
        lb0 = *(const float4*)(Bp + (long)r0        * K + c0);
        lb1 = *(const float4*)(Bp + (long)(r0 + 64) * K + c0);
        uint32_t* a = As[0];
        uint32_t* b = Bs[0];
        a[r0 * LDSS + c0 + 0] = f2tf32(la0.x);
        a[r0 * LDSS + c0 + 1] = f2tf32(la0.y);
        a[r0 * LDSS + c0 + 2] = f2tf32(la0.z);
        a[r0 * LDSS + c0 + 3] = f2tf32(la0.w);
        a[(r0 + 64) * LDSS + c0 + 0] = f2tf32(la1.x);
        a[(r0 + 64) * LDSS + c0 + 1] = f2tf32(la1.y);
        a[(r0 + 64) * LDSS + c0 + 2] = f2tf32(la1.z);
        a[(r0 + 64) * LDSS + c0 + 3] = f2tf32(la1.w);
        b[r0 * LDSS + c0 + 0] = f2tf32(lb0.x);
        b[r0 * LDSS + c0 + 1] = f2tf32(lb0.y);
        b[r0 * LDSS + c0 + 2] = f2tf32(lb0.z);
        b[r0 * LDSS + c0 + 3] = f2tf32(lb0.w);
        b[(r0 + 64) * LDSS + c0 + 0] = f2tf32(lb1.x);
        b[(r0 + 64) * LDSS + c0 + 1] = f2tf32(lb1.y);
        b[(r0 + 64) * LDSS + c0 + 2] = f2tf32(lb1.z);
        b[(r0 + 64) * LDSS + c0 + 3] = f2tf32(lb1.w);
    }
    __syncthreads();

    float acc[2][8][4];
    #pragma unroll
    for (int mi = 0; mi < 2; mi++)
        #pragma unroll
        for (int ni = 0; ni < 8; ni++)
            #pragma unroll
            for (int j = 0; j < 4; j++)
                acc[mi][ni][j] = 0.0f;

    #pragma unroll 1
    for (int kc = 0; kc < nchunks; kc++) {
        const int buf = kc & 1;

        // prefetch next chunk from global
        if (kc + 1 < nchunks) {
            const float* Ap = A + (kc + 1) * BK;
            const float* Bp = B + (kc + 1) * BK;
            la0 = *(const float4*)(Ap + (long)r0        * K + c0);
            la1 = *(const float4*)(Ap + (long)(r0 + 64) * K + c0);
            lb0 = *(const float4*)(Bp + (long)r0        * K + c0);
            lb1 = *(const float4*)(Bp + (long)(r0 + 64) * K + c0);
        }

        // compute from smem[buf]
        const uint32_t* as = As[buf];
        const uint32_t* bs = Bs[buf];
        #pragma unroll
        for (int ks = 0; ks < 2; ks++) {
            const int kof = ks * 8 + (lane & 3);
            uint32_t af[2][4], bf[8][2];
            #pragma unroll
            for (int mi = 0; mi < 2; mi++) {
                const int row = wm * 32 + mi * 16 + (lane >> 2);
                af[mi][0] = as[row * LDSS + kof];
                af[mi][1] = as[(row + 8) * LDSS + kof];
                af[mi][2] = as[row * LDSS + kof + 4];
                af[mi][3] = as[(row + 8) * LDSS + kof + 4];
            }
            #pragma unroll
            for (int ni = 0; ni < 8; ni++) {
                const int col = wn * 64 + ni * 8 + (lane >> 2);
                bf[ni][0] = bs[col * LDSS + kof];
                bf[ni][1] = bs[col * LDSS + kof + 4];
            }
            #pragma unroll
            for (int mi = 0; mi < 2; mi++)
                #pragma unroll
                for (int ni = 0; ni < 8; ni++)
                    asm volatile(
                        "mma.sync.aligned.m16n8k8.row.col.f32.tf32.tf32.f32 "
                        "{%0,%1,%2,%3}, {%4,%5,%6,%7}, {%8,%9}, {%0,%1,%2,%3};"
                        : "+f"(acc[mi][ni][0]), "+f"(acc[mi][ni][1]),
                          "+f"(acc[mi][ni][2]), "+f"(acc[mi][ni][3])
                        : "r"(af[mi][0]), "r"(af[mi][1]), "r"(af[mi][2]), "r"(af[mi][3]),
                          "r"(bf[ni][0]), "r"(bf[ni][1]));
        }

        // store prefetched chunk to the other buffer
        if (kc + 1 < nchunks) {
            uint32_t* a = As[buf ^ 1];
            uint32_t* b = Bs[buf ^ 1];
            a[r0 * LDSS + c0 + 0] = f2tf32(la0.x);
            a[r0 * LDSS + c0 + 1] = f2tf32(la0.y);
            a[r0 * LDSS + c0 + 2] = f2tf32(la0.z);
            a[r0 * LDSS + c0 + 3] = f2tf32(la0.w);
            a[(r0 + 64) * LDSS + c0 + 0] = f2tf32(la1.x);
            a[(r0 + 64) * LDSS + c0 + 1] = f2tf32(la1.y);
            a[(r0 + 64) * LDSS + c0 + 2] = f2tf32(la1.z);
            a[(r0 + 64) * LDSS + c0 + 3] = f2tf32(la1.w);
            b[r0 * LDSS + c0 + 0] = f2tf32(lb0.x);
            b[r0 * LDSS + c0 + 1] = f2tf32(lb0.y);
            b[r0 * LDSS + c0 + 2] = f2tf32(lb0.z);
            b[r0 * LDSS + c0 + 3] = f2tf32(lb0.w);
            b[(r0 + 64) * LDSS + c0 + 0] = f2tf32(lb1.x);
            b[(r0 + 64) * LDSS + c0 + 1] = f2tf32(lb1.y);
            b[(r0 + 64) * LDSS + c0 + 2] = f2tf32(lb1.z);
            b[(r0 + 64) * LDSS + c0 + 3] = f2tf32(lb1.w);
        }
        __syncthreads();
    }

    // Epilogue: c0,c1 at (row, col), c2,c3 at (row+8, col); col = 2*(lane&3)
    #pragma unroll
    for (int mi = 0; mi < 2; mi++) {
        const long row = (long)blockIdx.y * BM + wm * 32 + mi * 16 + (lane >> 2);
        #pragma unroll
        for (int ni = 0; ni < 8; ni++) {
            const long col = (long)blockIdx.x * BN + wn * 64 + ni * 8 + (lane & 3) * 2;
            float2 v0 = make_float2(acc[mi][ni][0], acc[mi][ni][1]);
            float2 v1 = make_float2(acc[mi][ni][2], acc[mi][ni][3]);
            if (RELU) {
                v0.x = fmaxf(v0.x, 0.0f); v0.y = fmaxf(v0.y, 0.0f);
                v1.x = fmaxf(v1.x, 0.0f); v1.y = fmaxf(v1.y, 0.0f);
            }
            *(float2*)(C + row * N + col)       = v0;
            *(float2*)(C + (row + 8) * N + col) = v1;
        }
    }
}

extern "C" void kernel_launch(void* const* d_in, const int* in_sizes, int n_in,
                              void* d_out, int out_size)
{
    (void)in_sizes; (void)n_in; (void)out_size;

    const float* x   = (const float*)d_in[0];  // (8,2048,256)
    const float* mem = (const float*)d_in[1];  // (8,1024,256)
    const float* W   = (const float*)d_in[2];  // (256,256)

    float* key = (float*)d_out;                      // 16384*256
    float* val = (float*)d_out + (long)16384 * 256;  // 16384*1024

    // GEMM 1: key = relu(x @ W^T)  M=16384 N=256 K=256
    {
        dim3 grid(256 / BN, 16384 / BM, 1);
        tf32_mma_nt<true><<<grid, 256>>>(x, W, key, 256, 256, 0, 0, 0);
    }
    // GEMM 2: val[b] = key[b] @ mem[b]^T  M=2048 N=1024 K=256, batch 8
    {
        dim3 grid(1024 / BN, 2048 / BM, 8);
        tf32_mma_nt<false><<<grid, 256>>>(
            key, mem, val, 256, 1024,
            (long)2048 * 256, (long)1024 * 256, (long)2048 * 1024);
    }
}

// round 5
// speedup vs baseline: 5.0649x; 1.1740x over previous
#include <cuda_runtime.h>
#include <cstdint>

// ReadingLayerReLU via mma.sync.m16n8k8 tf32 + ldmatrix fragment loads.
// key = relu(x @ W^T)        : M=16384, N=256,  K=256
// val[b] = key[b] @ mem[b]^T : M=2048,  N=1024, K=256, batch=8
// Both NT (K contiguous in both operands).

#define BM 128
#define BN 128
#define BK 16
#define LDSS 20   // smem row stride (words); r*20 mod 32 distinct for 8 rows -> LDSM conflict-free

__device__ __forceinline__ uint32_t f2tf32(float f) {
    uint32_t r;
    asm("cvt.rna.tf32.f32 %0, %1;" : "=r"(r) : "f"(f));
    return r;
}

__device__ __forceinline__ uint32_t s2u(const void* p) {
    uint32_t a;
    asm("{ .reg .u64 t; cvta.to.shared.u64 t, %1; cvt.u32.u64 %0, t; }" : "=r"(a) : "l"(p));
    return a;
}

__device__ __forceinline__ void ldsm4(uint32_t& r0, uint32_t& r1, uint32_t& r2, uint32_t& r3,
                                      uint32_t addr) {
    asm volatile("ldmatrix.sync.aligned.m8n8.x4.shared.b16 {%0,%1,%2,%3}, [%4];"
                 : "=r"(r0), "=r"(r1), "=r"(r2), "=r"(r3) : "r"(addr));
}

__device__ __forceinline__ uint4 cvt4(float4 v) {
    uint4 u;
    u.x = f2tf32(v.x); u.y = f2tf32(v.y); u.z = f2tf32(v.z); u.w = f2tf32(v.w);
    return u;
}

template<bool RELU>
__global__ __launch_bounds__(256, 2)
void tf32_mma_nt(const float* __restrict__ A, const float* __restrict__ B,
                 float* __restrict__ C, int K, int N,
                 long sA, long sB, long sC)
{
    __shared__ uint32_t As[2][BM * LDSS];
    __shared__ uint32_t Bs[2][BN * LDSS];

    const int tid  = threadIdx.x;
    const int lane = tid & 31;
    const int warp = tid >> 5;
    const int wm   = warp >> 1;    // 0..3 -> M offset wm*32
    const int wn   = warp & 1;     // 0..1 -> N offset wn*64

    A += (long)blockIdx.z * sA + (long)blockIdx.y * BM * K;
    B += (long)blockIdx.z * sB + (long)blockIdx.x * BN * K;
    C += (long)blockIdx.z * sC;

    // Global-load mapping: per matrix 128x16 floats = 512 float4.
    const int r0 = tid >> 2;          // 0..63 (rows r0, r0+64)
    const int c0 = (tid & 3) * 4;     // 0,4,8,12

    // STS word offsets (vectorized 128-bit stores)
    const uint32_t stsOffL = (uint32_t)(r0 * LDSS + c0);
    const uint32_t stsOffH = (uint32_t)((r0 + 64) * LDSS + c0);

    // LDSM per-lane address bases (byte offsets into a tile buffer)
    // A tiles (x4): t=lane>>3: {m0..+7,k0},{m0+8..,k0},{m0..,k0+4},{m0+8..,k0+4}
    const int la_rowA = wm * 32 + ((lane >> 3) & 1) * 8 + (lane & 7);
    const int la_colA = (lane >> 4) * 4;
    const uint32_t aBase = (uint32_t)(la_rowA * LDSS + la_colA) * 4u;
    // B tiles (x4): t=lane>>3: {n0..+7,k0},{n0..,k0+4},{n0+8..,k0},{n0+8..,k0+4}
    const int la_rowB = wn * 64 + (lane >> 4) * 8 + (lane & 7);
    const int la_colB = ((lane >> 3) & 1) * 4;
    const uint32_t bBase = (uint32_t)(la_rowB * LDSS + la_colB) * 4u;

    const uint32_t sbA0 = s2u(As[0]);
    const uint32_t sbA1 = s2u(As[1]);
    const uint32_t sbB0 = s2u(Bs[0]);
    const uint32_t sbB1 = s2u(Bs[1]);

    float4 la0, la1, lb0, lb1;
    const int nchunks = K / BK;       // 16

    // prologue: chunk 0 -> buf 0
    la0 = *(const float4*)(A + (long)r0        * K + c0);
    la1 = *(const float4*)(A + (long)(r0 + 64) * K + c0);
    lb0 = *(const float4*)(B + (long)r0        * K + c0);
    lb1 = *(const float4*)(B + (long)(r0 + 64) * K + c0);
    *(uint4*)&As[0][stsOffL] = cvt4(la0);
    *(uint4*)&As[0][stsOffH] = cvt4(la1);
    *(uint4*)&Bs[0][stsOffL] = cvt4(lb0);
    *(uint4*)&Bs[0][stsOffH] = cvt4(lb1);
    __syncthreads();

    float acc[2][8][4];
    #pragma unroll
    for (int mi = 0; mi < 2; mi++)
        #pragma unroll
        for (int ni = 0; ni < 8; ni++)
            #pragma unroll
            for (int j = 0; j < 4; j++)
                acc[mi][ni][j] = 0.0f;

    #pragma unroll 1
    for (int kc = 0; kc < nchunks; kc++) {
        const int buf = kc & 1;
        const uint32_t aS = buf ? sbA1 : sbA0;
        const uint32_t bS = buf ? sbB1 : sbB0;

        // prefetch next chunk from global
        if (kc + 1 < nchunks) {
            const float* Ap = A + (kc + 1) * BK;
            const float* Bp = B + (kc + 1) * BK;
            la0 = *(const float4*)(Ap + (long)r0        * K + c0);
            la1 = *(const float4*)(Ap + (long)(r0 + 64) * K + c0);
            lb0 = *(const float4*)(Bp + (long)r0        * K + c0);
            lb1 = *(const float4*)(Bp + (long)(r0 + 64) * K + c0);
        }

        #pragma unroll
        for (int ks = 0; ks < 2; ks++) {
            const uint32_t kByte = (uint32_t)(ks * 8) * 4u;
            uint32_t af[2][4], bf[8][2];
            // A: one LDSM.x4 per mi (4 tiles each)
            #pragma unroll
            for (int mi = 0; mi < 2; mi++)
                ldsm4(af[mi][0], af[mi][1], af[mi][2], af[mi][3],
                      aS + aBase + (uint32_t)(mi * 16 * LDSS) * 4u + kByte);
            // B: one LDSM.x4 per ni-pair: regs = {bf[2j][0], bf[2j][1], bf[2j+1][0], bf[2j+1][1]}
            #pragma unroll
            for (int j = 0; j < 4; j++)
                ldsm4(bf[2 * j][0], bf[2 * j][1], bf[2 * j + 1][0], bf[2 * j + 1][1],
                      bS + bBase + (uint32_t)(j * 16 * LDSS) * 4u + kByte);

            #pragma unroll
            for (int mi = 0; mi < 2; mi++)
                #pragma unroll
                for (int ni = 0; ni < 8; ni++)
                    asm volatile(
                        "mma.sync.aligned.m16n8k8.row.col.f32.tf32.tf32.f32 "
                        "{%0,%1,%2,%3}, {%4,%5,%6,%7}, {%8,%9}, {%0,%1,%2,%3};"
                        : "+f"(acc[mi][ni][0]), "+f"(acc[mi][ni][1]),
                          "+f"(acc[mi][ni][2]), "+f"(acc[mi][ni][3])
                        : "r"(af[mi][0]), "r"(af[mi][1]), "r"(af[mi][2]), "r"(af[mi][3]),
                          "r"(bf[ni][0]), "r"(bf[ni][1]));
        }

        // store prefetched chunk to the other buffer
        if (kc + 1 < nchunks) {
            uint32_t* a = As[buf ^ 1];
            uint32_t* b = Bs[buf ^ 1];
            *(uint4*)&a[stsOffL] = cvt4(la0);
            *(uint4*)&a[stsOffH] = cvt4(la1);
            *(uint4*)&b[stsOffL] = cvt4(lb0);
            *(uint4*)&b[stsOffH] = cvt4(lb1);
        }
        __syncthreads();
    }

    // Epilogue: c0,c1 at (row, col), c2,c3 at (row+8, col); col = 2*(lane&3)
    #pragma unroll
    for (int mi = 0; mi < 2; mi++) {
        const long row = (long)blockIdx.y * BM + wm * 32 + mi * 16 + (lane >> 2);
        #pragma unroll
        for (int ni = 0; ni < 8; ni++) {
            const long col = (long)blockIdx.x * BN + wn * 64 + ni * 8 + (lane & 3) * 2;
            float2 v0 = make_float2(acc[mi][ni][0], acc[mi][ni][1]);
            float2 v1 = make_float2(acc[mi][ni][2], acc[mi][ni][3]);
            if (RELU) {
                v0.x = fmaxf(v0.x, 0.0f); v0.y = fmaxf(v0.y, 0.0f);
                v1.x = fmaxf(v1.x, 0.0f); v1.y = fmaxf(v1.y, 0.0f);
            }
            *(float2*)(C + row * N + col)       = v0;
            *(float2*)(C + (row + 8) * N + col) = v1;
        }
    }
}

extern "C" void kernel_launch(void* const* d_in, const int* in_sizes, int n_in,
                              void* d_out, int out_size)
{
    (void)in_sizes; (void)n_in; (void)out_size;

    const float* x   = (const float*)d_in[0];  // (8,2048,256)
    const float* mem = (const float*)d_in[1];  // (8,1024,256)
    const float* W   = (const float*)d_in[2];  // (256,256)

    float* key = (float*)d_out;                      // 16384*256
    float* val = (float*)d_out + (long)16384 * 256;  // 16384*1024

    // GEMM 1: key = relu(x @ W^T)  M=16384 N=256 K=256
    {
        dim3 grid(256 / BN, 16384 / BM, 1);
        tf32_mma_nt<true><<<grid, 256>>>(x, W, key, 256, 256, 0, 0, 0);
    }
    // GEMM 2: val[b] = key[b] @ mem[b]^T  M=2048 N=1024 K=256, batch 8
    {
        dim3 grid(1024 / BN, 2048 / BM, 8);
        tf32_mma_nt<false><<<grid, 256>>>(
            key, mem, val, 256, 1024,
            (long)2048 * 256, (long)1024 * 256, (long)2048 * 1024);
    }
}